// round 1
// baseline (speedup 1.0000x reference)
#include <cuda_runtime.h>

// Fused Swin-style window attention, fp32 baseline.
// Shapes (fixed by setup_inputs): B=4, H=W=256, C=192, ws=8, nh=6, hd=32.
// One CTA = one 8x8 window (64 tokens). 4096 CTAs, 256 threads each.

#define B_   4
#define H_   256
#define W_   256
#define C_   192
#define NH_  6
#define HD_  32
#define WS_  8
#define T_   64     // tokens per window

// ---- shared memory layout (floats) ----
#define XS_STRIDE 68                       // [c][t] transposed x; pad 68 (=4 mod 32, float4 ok)
#define XS_OFF    0
#define XS_SIZE   (C_ * XS_STRIDE)         // 13056
#define QKV_ROW   193                      // [t][c] rows; odd pad -> 2-way max conflicts on column reads
#define QKV_OFF   XS_SIZE
#define QKV_SIZE  (3 * T_ * QKV_ROW)       // 37056
#define WS_STRIDE 196                      // weight K-tile [16][196]
#define S_STRIDE  68                       // score matrix [64][68]
#define WSU_OFF   (QKV_OFF + QKV_SIZE)     // 50112 (union: weight tile / S)
#define WSU_SIZE  (T_ * S_STRIDE)          // 4352 >= 16*196=3136
#define RPB_OFF   (WSU_OFF + WSU_SIZE)     // 54464
#define RPB_SIZE  (225 * NH_)              // 1350
#define SMEM_FLOATS (RPB_OFF + RPB_SIZE)   // 55814
#define SMEM_BYTES  (SMEM_FLOATS * 4)      // 223256 < 232448 limit

__global__ void __launch_bounds__(256, 1)
swin_win_attn_kernel(const float* __restrict__ x,
                     const float* __restrict__ qkv_w,
                     const float* __restrict__ proj_w,
                     const float* __restrict__ proj_b,
                     const float* __restrict__ rpb,
                     float* __restrict__ outp)
{
    extern __shared__ float sm[];
    float* xs   = sm + XS_OFF;   // x transposed [c][t]; later reused as attn-out transposed
    float* qkvs = sm + QKV_OFF;  // q|k|v, each [64][QKV_ROW]
    float* wsb  = sm + WSU_OFF;  // weight K-tile [16][WS_STRIDE]  /  S [64][S_STRIDE]
    float* rpbs = sm + RPB_OFF;  // rpb table [225][6]

    const int tid = threadIdx.x;
    const int win = blockIdx.x;
    const int b   = win >> 10;
    const int wy  = (win >> 5) & 31;
    const int wx  = win & 31;
    const long pix0 = ((long)b * H_ + (long)wy * WS_) * W_ + (long)wx * WS_;

    // ---------------- Phase 1: stage x window (transposed) + rpb table ----------------
    #pragma unroll 2
    for (int i = tid; i < T_ * 48; i += 256) {
        const int t  = i / 48;
        const int c4 = (i % 48) * 4;
        const int py = t >> 3, px = t & 7;
        const float4 v = *(const float4*)(x + (pix0 + (long)py * W_ + px) * C_ + c4);
        xs[(c4 + 0) * XS_STRIDE + t] = v.x;
        xs[(c4 + 1) * XS_STRIDE + t] = v.y;
        xs[(c4 + 2) * XS_STRIDE + t] = v.z;
        xs[(c4 + 3) * XS_STRIDE + t] = v.w;
    }
    for (int i = tid; i < 225 * NH_; i += 256) rpbs[i] = rpb[i];

    const int gtx  = tid % 24;       // 24 col-groups of 8 -> 192 cols
    const int gty  = tid / 24;       // 8 row-groups of 8  -> 64 rows (gty<8 active)
    const bool gact = (gty < 8);

    // ---------------- Phase 2: QKV = x @ qkv_w^T  (3 passes of 64x192, K=192) ----------------
    for (int s = 0; s < 3; ++s) {
        float acc[8][8];
        #pragma unroll
        for (int i = 0; i < 8; ++i)
            #pragma unroll
            for (int j = 0; j < 8; ++j) acc[i][j] = 0.f;

        const float* wptr = qkv_w + (size_t)s * 192 * 192;
        for (int kc = 0; kc < 192; kc += 16) {
            __syncthreads();
            // stage weight K-tile: wsb[kk][c] = wptr[c*192 + kc + kk]
            #pragma unroll 3
            for (int i = tid; i < 768; i += 256) {
                const int c  = i >> 2;
                const int k4 = (i & 3) * 4;
                const float4 v = *(const float4*)(wptr + c * 192 + kc + k4);
                wsb[(k4 + 0) * WS_STRIDE + c] = v.x;
                wsb[(k4 + 1) * WS_STRIDE + c] = v.y;
                wsb[(k4 + 2) * WS_STRIDE + c] = v.z;
                wsb[(k4 + 3) * WS_STRIDE + c] = v.w;
            }
            __syncthreads();
            if (gact) {
                const float* xcol = xs + kc * XS_STRIDE + gty * 8;
                const float* wrow = wsb + gtx * 8;
                #pragma unroll
                for (int kk = 0; kk < 16; ++kk) {
                    const float4 a0 = *(const float4*)(xcol + kk * XS_STRIDE);
                    const float4 a1 = *(const float4*)(xcol + kk * XS_STRIDE + 4);
                    const float4 b0 = *(const float4*)(wrow + kk * WS_STRIDE);
                    const float4 b1 = *(const float4*)(wrow + kk * WS_STRIDE + 4);
                    const float a[8]  = {a0.x, a0.y, a0.z, a0.w, a1.x, a1.y, a1.z, a1.w};
                    const float bb[8] = {b0.x, b0.y, b0.z, b0.w, b1.x, b1.y, b1.z, b1.w};
                    #pragma unroll
                    for (int i = 0; i < 8; ++i)
                        #pragma unroll
                        for (int j = 0; j < 8; ++j)
                            acc[i][j] = fmaf(a[i], bb[j], acc[i][j]);
                }
            }
        }
        if (gact) {
            const float mul = (s == 0) ? 0.17677669529663687f : 1.0f;  // q pre-scaled by 1/sqrt(hd)
            float* dst = qkvs + (size_t)s * T_ * QKV_ROW;
            #pragma unroll
            for (int i = 0; i < 8; ++i)
                #pragma unroll
                for (int j = 0; j < 8; ++j)
                    dst[(gty * 8 + i) * QKV_ROW + gtx * 8 + j] = acc[i][j] * mul;
        }
    }
    __syncthreads();

    // ---------------- Phase 3: per-head attention ----------------
    const float* q_s = qkvs;
    const float* k_s = qkvs + T_ * QKV_ROW;
    const float* v_s = qkvs + 2 * T_ * QKV_ROW;
    float* S  = wsb;   // [64][S_STRIDE]
    float* ao = xs;    // attn output transposed [c][t], reuse xs region

    const int si = (tid >> 4) * 4;    // 4 rows per thread
    const int sj = (tid & 15) * 4;    // 4 cols per thread (S phase)
    const int ci = (tid & 15) * 2;    // 2 cols per thread (PV phase)

    for (int h = 0; h < NH_; ++h) {
        const int hc = h * HD_;
        // ---- S = q @ k^T + bias ----
        {
            float acc[4][4];
            #pragma unroll
            for (int i = 0; i < 4; ++i)
                #pragma unroll
                for (int j = 0; j < 4; ++j) acc[i][j] = 0.f;
            #pragma unroll 8
            for (int d = 0; d < HD_; ++d) {
                float a[4], bb[4];
                #pragma unroll
                for (int i = 0; i < 4; ++i) a[i]  = q_s[(si + i) * QKV_ROW + hc + d];
                #pragma unroll
                for (int j = 0; j < 4; ++j) bb[j] = k_s[(sj + j) * QKV_ROW + hc + d];
                #pragma unroll
                for (int i = 0; i < 4; ++i)
                    #pragma unroll
                    for (int j = 0; j < 4; ++j)
                        acc[i][j] = fmaf(a[i], bb[j], acc[i][j]);
            }
            #pragma unroll
            for (int i = 0; i < 4; ++i) {
                const int p = si + i;
                #pragma unroll
                for (int j = 0; j < 4; ++j) {
                    const int qq  = sj + j;
                    const int dy  = (p >> 3) - (qq >> 3);
                    const int dx  = (p & 7)  - (qq & 7);
                    const int idx = (dy + 7) * 15 + (dx + 7);
                    S[p * S_STRIDE + qq] = acc[i][j] + rpbs[idx * NH_ + h];
                }
            }
        }
        __syncthreads();
        // ---- row softmax (stable) ----
        if (tid < 64) {
            float* row = S + tid * S_STRIDE;
            float m = -1e30f;
            #pragma unroll 8
            for (int j = 0; j < 64; ++j) m = fmaxf(m, row[j]);
            float sum = 0.f;
            #pragma unroll 8
            for (int j = 0; j < 64; ++j) { const float e = __expf(row[j] - m); row[j] = e; sum += e; }
            const float inv = 1.f / sum;
            #pragma unroll 8
            for (int j = 0; j < 64; ++j) row[j] *= inv;
        }
        __syncthreads();
        // ---- O = P @ v, store transposed into ao ----
        {
            float o0[4], o1[4];
            #pragma unroll
            for (int i = 0; i < 4; ++i) { o0[i] = 0.f; o1[i] = 0.f; }
            #pragma unroll 4
            for (int j = 0; j < 64; ++j) {
                const float v0 = v_s[j * QKV_ROW + hc + ci];
                const float v1 = v_s[j * QKV_ROW + hc + ci + 1];
                #pragma unroll
                for (int i = 0; i < 4; ++i) {
                    const float p = S[(si + i) * S_STRIDE + j];
                    o0[i] = fmaf(p, v0, o0[i]);
                    o1[i] = fmaf(p, v1, o1[i]);
                }
            }
            #pragma unroll
            for (int i = 0; i < 4; ++i) {
                ao[(hc + ci + 0) * XS_STRIDE + si + i] = o0[i];
                ao[(hc + ci + 1) * XS_STRIDE + si + i] = o1[i];
            }
        }
        __syncthreads();
    }

    // ---------------- Phase 4: proj = attn_out @ proj_w^T + b, scatter to output ----------------
    {
        float acc[8][8];
        #pragma unroll
        for (int i = 0; i < 8; ++i)
            #pragma unroll
            for (int j = 0; j < 8; ++j) acc[i][j] = 0.f;

        for (int kc = 0; kc < 192; kc += 16) {
            __syncthreads();
            #pragma unroll 3
            for (int i = tid; i < 768; i += 256) {
                const int c  = i >> 2;
                const int k4 = (i & 3) * 4;
                const float4 v = *(const float4*)(proj_w + c * 192 + kc + k4);
                wsb[(k4 + 0) * WS_STRIDE + c] = v.x;
                wsb[(k4 + 1) * WS_STRIDE + c] = v.y;
                wsb[(k4 + 2) * WS_STRIDE + c] = v.z;
                wsb[(k4 + 3) * WS_STRIDE + c] = v.w;
            }
            __syncthreads();
            if (gact) {
                const float* acol = ao + kc * XS_STRIDE + gty * 8;
                const float* wrow = wsb + gtx * 8;
                #pragma unroll
                for (int kk = 0; kk < 16; ++kk) {
                    const float4 a0 = *(const float4*)(acol + kk * XS_STRIDE);
                    const float4 a1 = *(const float4*)(acol + kk * XS_STRIDE + 4);
                    const float4 b0 = *(const float4*)(wrow + kk * WS_STRIDE);
                    const float4 b1 = *(const float4*)(wrow + kk * WS_STRIDE + 4);
                    const float a[8]  = {a0.x, a0.y, a0.z, a0.w, a1.x, a1.y, a1.z, a1.w};
                    const float bb[8] = {b0.x, b0.y, b0.z, b0.w, b1.x, b1.y, b1.z, b1.w};
                    #pragma unroll
                    for (int i = 0; i < 8; ++i)
                        #pragma unroll
                        for (int j = 0; j < 8; ++j)
                            acc[i][j] = fmaf(a[i], bb[j], acc[i][j]);
                }
            }
        }
        if (gact) {
            float pb[8];
            #pragma unroll
            for (int j = 0; j < 8; ++j) pb[j] = proj_b[gtx * 8 + j];
            #pragma unroll
            for (int i = 0; i < 8; ++i) {
                const int t  = gty * 8 + i;
                const int py = t >> 3, px = t & 7;
                float* dst = outp + (pix0 + (long)py * W_ + px) * C_ + gtx * 8;
                float4 r0, r1;
                r0.x = acc[i][0] + pb[0]; r0.y = acc[i][1] + pb[1];
                r0.z = acc[i][2] + pb[2]; r0.w = acc[i][3] + pb[3];
                r1.x = acc[i][4] + pb[4]; r1.y = acc[i][5] + pb[5];
                r1.z = acc[i][6] + pb[6]; r1.w = acc[i][7] + pb[7];
                *(float4*)(dst)     = r0;
                *(float4*)(dst + 4) = r1;
            }
        }
    }
}

extern "C" void kernel_launch(void* const* d_in, const int* in_sizes, int n_in,
                              void* d_out, int out_size)
{
    const float* x      = (const float*)d_in[0];
    const float* qkv_w  = (const float*)d_in[1];
    const float* proj_w = (const float*)d_in[2];
    const float* proj_b = (const float*)d_in[3];
    const float* rpb    = (const float*)d_in[4];
    // d_in[5], d_in[6] are H, W scalars (fixed 256x256 for this problem)

    cudaFuncSetAttribute(swin_win_attn_kernel,
                         cudaFuncAttributeMaxDynamicSharedMemorySize, SMEM_BYTES);

    const int n_windows = B_ * (H_ / WS_) * (W_ / WS_);  // 4096
    swin_win_attn_kernel<<<n_windows, 256, SMEM_BYTES>>>(
        x, qkv_w, proj_w, proj_b, rpb, (float*)d_out);
}

// round 2
// speedup vs baseline: 1.0005x; 1.0005x over previous
#include <cuda_runtime.h>

// Fused Swin-style window attention, fp32 baseline.
// Shapes (fixed by setup_inputs): B=4, H=W=256, C=192, ws=8, nh=6, hd=32.
// One CTA = one 8x8 window (64 tokens). 4096 CTAs, 256 threads each.

#define B_   4
#define H_   256
#define W_   256
#define C_   192
#define NH_  6
#define HD_  32
#define WS_  8
#define T_   64     // tokens per window

// ---- shared memory layout (floats) ----
#define XS_STRIDE 68                       // [c][t] transposed x; pad 68 (=4 mod 32, float4 ok)
#define XS_OFF    0
#define XS_SIZE   (C_ * XS_STRIDE)         // 13056
#define QKV_ROW   193                      // [t][c] rows; odd pad -> 2-way max conflicts on column reads
#define QKV_OFF   XS_SIZE
#define QKV_SIZE  (3 * T_ * QKV_ROW)       // 37056
#define WS_STRIDE 196                      // weight K-tile [16][196]
#define S_STRIDE  68                       // score matrix [64][68]
#define WSU_OFF   (QKV_OFF + QKV_SIZE)     // 50112 (union: weight tile / S)
#define WSU_SIZE  (T_ * S_STRIDE)          // 4352 >= 16*196=3136
#define RPB_OFF   (WSU_OFF + WSU_SIZE)     // 54464
#define RPB_SIZE  (225 * NH_)              // 1350
#define SMEM_FLOATS (RPB_OFF + RPB_SIZE)   // 55814
#define SMEM_BYTES  (SMEM_FLOATS * 4)      // 223256 < 232448 limit

__global__ void __launch_bounds__(256, 1)
swin_win_attn_kernel(const float* __restrict__ x,
                     const float* __restrict__ qkv_w,
                     const float* __restrict__ proj_w,
                     const float* __restrict__ proj_b,
                     const float* __restrict__ rpb,
                     float* __restrict__ outp)
{
    extern __shared__ float sm[];
    float* xs   = sm + XS_OFF;   // x transposed [c][t]; later reused as attn-out transposed
    float* qkvs = sm + QKV_OFF;  // q|k|v, each [64][QKV_ROW]
    float* wsb  = sm + WSU_OFF;  // weight K-tile [16][WS_STRIDE]  /  S [64][S_STRIDE]
    float* rpbs = sm + RPB_OFF;  // rpb table [225][6]

    const int tid = threadIdx.x;
    const int win = blockIdx.x;
    const int b   = win >> 10;
    const int wy  = (win >> 5) & 31;
    const int wx  = win & 31;
    const long pix0 = ((long)b * H_ + (long)wy * WS_) * W_ + (long)wx * WS_;

    // ---------------- Phase 1: stage x window (transposed) + rpb table ----------------
    #pragma unroll 2
    for (int i = tid; i < T_ * 48; i += 256) {
        const int t  = i / 48;
        const int c4 = (i % 48) * 4;
        const int py = t >> 3, px = t & 7;
        const float4 v = *(const float4*)(x + (pix0 + (long)py * W_ + px) * C_ + c4);
        xs[(c4 + 0) * XS_STRIDE + t] = v.x;
        xs[(c4 + 1) * XS_STRIDE + t] = v.y;
        xs[(c4 + 2) * XS_STRIDE + t] = v.z;
        xs[(c4 + 3) * XS_STRIDE + t] = v.w;
    }
    for (int i = tid; i < 225 * NH_; i += 256) rpbs[i] = rpb[i];

    const int gtx  = tid % 24;       // 24 col-groups of 8 -> 192 cols
    const int gty  = tid / 24;       // 8 row-groups of 8  -> 64 rows (gty<8 active)
    const bool gact = (gty < 8);

    // ---------------- Phase 2: QKV = x @ qkv_w^T  (3 passes of 64x192, K=192) ----------------
    for (int s = 0; s < 3; ++s) {
        float acc[8][8];
        #pragma unroll
        for (int i = 0; i < 8; ++i)
            #pragma unroll
            for (int j = 0; j < 8; ++j) acc[i][j] = 0.f;

        const float* wptr = qkv_w + (size_t)s * 192 * 192;
        for (int kc = 0; kc < 192; kc += 16) {
            __syncthreads();
            // stage weight K-tile: wsb[kk][c] = wptr[c*192 + kc + kk]
            #pragma unroll 3
            for (int i = tid; i < 768; i += 256) {
                const int c  = i >> 2;
                const int k4 = (i & 3) * 4;
                const float4 v = *(const float4*)(wptr + c * 192 + kc + k4);
                wsb[(k4 + 0) * WS_STRIDE + c] = v.x;
                wsb[(k4 + 1) * WS_STRIDE + c] = v.y;
                wsb[(k4 + 2) * WS_STRIDE + c] = v.z;
                wsb[(k4 + 3) * WS_STRIDE + c] = v.w;
            }
            __syncthreads();
            if (gact) {
                const float* xcol = xs + kc * XS_STRIDE + gty * 8;
                const float* wrow = wsb + gtx * 8;
                #pragma unroll
                for (int kk = 0; kk < 16; ++kk) {
                    const float4 a0 = *(const float4*)(xcol + kk * XS_STRIDE);
                    const float4 a1 = *(const float4*)(xcol + kk * XS_STRIDE + 4);
                    const float4 b0 = *(const float4*)(wrow + kk * WS_STRIDE);
                    const float4 b1 = *(const float4*)(wrow + kk * WS_STRIDE + 4);
                    const float a[8]  = {a0.x, a0.y, a0.z, a0.w, a1.x, a1.y, a1.z, a1.w};
                    const float bb[8] = {b0.x, b0.y, b0.z, b0.w, b1.x, b1.y, b1.z, b1.w};
                    #pragma unroll
                    for (int i = 0; i < 8; ++i)
                        #pragma unroll
                        for (int j = 0; j < 8; ++j)
                            acc[i][j] = fmaf(a[i], bb[j], acc[i][j]);
                }
            }
        }
        if (gact) {
            const float mul = (s == 0) ? 0.17677669529663687f : 1.0f;  // q pre-scaled by 1/sqrt(hd)
            float* dst = qkvs + (size_t)s * T_ * QKV_ROW;
            #pragma unroll
            for (int i = 0; i < 8; ++i)
                #pragma unroll
                for (int j = 0; j < 8; ++j)
                    dst[(gty * 8 + i) * QKV_ROW + gtx * 8 + j] = acc[i][j] * mul;
        }
    }
    __syncthreads();

    // ---------------- Phase 3: per-head attention ----------------
    const float* q_s = qkvs;
    const float* k_s = qkvs + T_ * QKV_ROW;
    const float* v_s = qkvs + 2 * T_ * QKV_ROW;
    float* S  = wsb;   // [64][S_STRIDE]
    float* ao = xs;    // attn output transposed [c][t], reuse xs region

    const int si = (tid >> 4) * 4;    // 4 rows per thread
    const int sj = (tid & 15) * 4;    // 4 cols per thread (S phase)
    const int ci = (tid & 15) * 2;    // 2 cols per thread (PV phase)

    for (int h = 0; h < NH_; ++h) {
        const int hc = h * HD_;
        // ---- S = q @ k^T + bias ----
        {
            float acc[4][4];
            #pragma unroll
            for (int i = 0; i < 4; ++i)
                #pragma unroll
                for (int j = 0; j < 4; ++j) acc[i][j] = 0.f;
            #pragma unroll 8
            for (int d = 0; d < HD_; ++d) {
                float a[4], bb[4];
                #pragma unroll
                for (int i = 0; i < 4; ++i) a[i]  = q_s[(si + i) * QKV_ROW + hc + d];
                #pragma unroll
                for (int j = 0; j < 4; ++j) bb[j] = k_s[(sj + j) * QKV_ROW + hc + d];
                #pragma unroll
                for (int i = 0; i < 4; ++i)
                    #pragma unroll
                    for (int j = 0; j < 4; ++j)
                        acc[i][j] = fmaf(a[i], bb[j], acc[i][j]);
            }
            #pragma unroll
            for (int i = 0; i < 4; ++i) {
                const int p = si + i;
                #pragma unroll
                for (int j = 0; j < 4; ++j) {
                    const int qq  = sj + j;
                    const int dy  = (p >> 3) - (qq >> 3);
                    const int dx  = (p & 7)  - (qq & 7);
                    const int idx = (dy + 7) * 15 + (dx + 7);
                    S[p * S_STRIDE + qq] = acc[i][j] + rpbs[idx * NH_ + h];
                }
            }
        }
        __syncthreads();
        // ---- row softmax (stable) ----
        if (tid < 64) {
            float* row = S + tid * S_STRIDE;
            float m = -1e30f;
            #pragma unroll 8
            for (int j = 0; j < 64; ++j) m = fmaxf(m, row[j]);
            float sum = 0.f;
            #pragma unroll 8
            for (int j = 0; j < 64; ++j) { const float e = __expf(row[j] - m); row[j] = e; sum += e; }
            const float inv = 1.f / sum;
            #pragma unroll 8
            for (int j = 0; j < 64; ++j) row[j] *= inv;
        }
        __syncthreads();
        // ---- O = P @ v, store transposed into ao ----
        {
            float o0[4], o1[4];
            #pragma unroll
            for (int i = 0; i < 4; ++i) { o0[i] = 0.f; o1[i] = 0.f; }
            #pragma unroll 4
            for (int j = 0; j < 64; ++j) {
                const float v0 = v_s[j * QKV_ROW + hc + ci];
                const float v1 = v_s[j * QKV_ROW + hc + ci + 1];
                #pragma unroll
                for (int i = 0; i < 4; ++i) {
                    const float p = S[(si + i) * S_STRIDE + j];
                    o0[i] = fmaf(p, v0, o0[i]);
                    o1[i] = fmaf(p, v1, o1[i]);
                }
            }
            #pragma unroll
            for (int i = 0; i < 4; ++i) {
                ao[(hc + ci + 0) * XS_STRIDE + si + i] = o0[i];
                ao[(hc + ci + 1) * XS_STRIDE + si + i] = o1[i];
            }
        }
        __syncthreads();
    }

    // ---------------- Phase 4: proj = attn_out @ proj_w^T + b, scatter to output ----------------
    {
        float acc[8][8];
        #pragma unroll
        for (int i = 0; i < 8; ++i)
            #pragma unroll
            for (int j = 0; j < 8; ++j) acc[i][j] = 0.f;

        for (int kc = 0; kc < 192; kc += 16) {
            __syncthreads();
            #pragma unroll 3
            for (int i = tid; i < 768; i += 256) {
                const int c  = i >> 2;
                const int k4 = (i & 3) * 4;
                const float4 v = *(const float4*)(proj_w + c * 192 + kc + k4);
                wsb[(k4 + 0) * WS_STRIDE + c] = v.x;
                wsb[(k4 + 1) * WS_STRIDE + c] = v.y;
                wsb[(k4 + 2) * WS_STRIDE + c] = v.z;
                wsb[(k4 + 3) * WS_STRIDE + c] = v.w;
            }
            __syncthreads();
            if (gact) {
                const float* acol = ao + kc * XS_STRIDE + gty * 8;
                const float* wrow = wsb + gtx * 8;
                #pragma unroll
                for (int kk = 0; kk < 16; ++kk) {
                    const float4 a0 = *(const float4*)(acol + kk * XS_STRIDE);
                    const float4 a1 = *(const float4*)(acol + kk * XS_STRIDE + 4);
                    const float4 b0 = *(const float4*)(wrow + kk * WS_STRIDE);
                    const float4 b1 = *(const float4*)(wrow + kk * WS_STRIDE + 4);
                    const float a[8]  = {a0.x, a0.y, a0.z, a0.w, a1.x, a1.y, a1.z, a1.w};
                    const float bb[8] = {b0.x, b0.y, b0.z, b0.w, b1.x, b1.y, b1.z, b1.w};
                    #pragma unroll
                    for (int i = 0; i < 8; ++i)
                        #pragma unroll
                        for (int j = 0; j < 8; ++j)
                            acc[i][j] = fmaf(a[i], bb[j], acc[i][j]);
                }
            }
        }
        if (gact) {
            float pb[8];
            #pragma unroll
            for (int j = 0; j < 8; ++j) pb[j] = proj_b[gtx * 8 + j];
            #pragma unroll
            for (int i = 0; i < 8; ++i) {
                const int t  = gty * 8 + i;
                const int py = t >> 3, px = t & 7;
                float* dst = outp + (pix0 + (long)py * W_ + px) * C_ + gtx * 8;
                float4 r0, r1;
                r0.x = acc[i][0] + pb[0]; r0.y = acc[i][1] + pb[1];
                r0.z = acc[i][2] + pb[2]; r0.w = acc[i][3] + pb[3];
                r1.x = acc[i][4] + pb[4]; r1.y = acc[i][5] + pb[5];
                r1.z = acc[i][6] + pb[6]; r1.w = acc[i][7] + pb[7];
                *(float4*)(dst)     = r0;
                *(float4*)(dst + 4) = r1;
            }
        }
    }
}

extern "C" void kernel_launch(void* const* d_in, const int* in_sizes, int n_in,
                              void* d_out, int out_size)
{
    const float* x      = (const float*)d_in[0];
    const float* qkv_w  = (const float*)d_in[1];
    const float* proj_w = (const float*)d_in[2];
    const float* proj_b = (const float*)d_in[3];
    const float* rpb    = (const float*)d_in[4];
    // d_in[5], d_in[6] are H, W scalars (fixed 256x256 for this problem)

    cudaFuncSetAttribute(swin_win_attn_kernel,
                         cudaFuncAttributeMaxDynamicSharedMemorySize, SMEM_BYTES);

    const int n_windows = B_ * (H_ / WS_) * (W_ / WS_);  // 4096
    swin_win_attn_kernel<<<n_windows, 256, SMEM_BYTES>>>(
        x, qkv_w, proj_w, proj_b, rpb, (float*)d_out);
}

// round 3
// speedup vs baseline: 1.0009x; 1.0004x over previous
#include <cuda_runtime.h>

// Fused Swin-style window attention, fp32 baseline.
// Shapes (fixed by setup_inputs): B=4, H=W=256, C=192, ws=8, nh=6, hd=32.
// One CTA = one 8x8 window (64 tokens). 4096 CTAs, 256 threads each.

#define B_   4
#define H_   256
#define W_   256
#define C_   192
#define NH_  6
#define HD_  32
#define WS_  8
#define T_   64     // tokens per window

// ---- shared memory layout (floats) ----
#define XS_STRIDE 68                       // [c][t] transposed x; pad 68 (=4 mod 32, float4 ok)
#define XS_OFF    0
#define XS_SIZE   (C_ * XS_STRIDE)         // 13056
#define QKV_ROW   193                      // [t][c] rows; odd pad -> 2-way max conflicts on column reads
#define QKV_OFF   XS_SIZE
#define QKV_SIZE  (3 * T_ * QKV_ROW)       // 37056
#define WS_STRIDE 196                      // weight K-tile [16][196]
#define S_STRIDE  68                       // score matrix [64][68]
#define WSU_OFF   (QKV_OFF + QKV_SIZE)     // 50112 (union: weight tile / S)
#define WSU_SIZE  (T_ * S_STRIDE)          // 4352 >= 16*196=3136
#define RPB_OFF   (WSU_OFF + WSU_SIZE)     // 54464
#define RPB_SIZE  (225 * NH_)              // 1350
#define SMEM_FLOATS (RPB_OFF + RPB_SIZE)   // 55814
#define SMEM_BYTES  (SMEM_FLOATS * 4)      // 223256 < 232448 limit

__global__ void __launch_bounds__(256, 1)
swin_win_attn_kernel(const float* __restrict__ x,
                     const float* __restrict__ qkv_w,
                     const float* __restrict__ proj_w,
                     const float* __restrict__ proj_b,
                     const float* __restrict__ rpb,
                     float* __restrict__ outp)
{
    extern __shared__ float sm[];
    float* xs   = sm + XS_OFF;   // x transposed [c][t]; later reused as attn-out transposed
    float* qkvs = sm + QKV_OFF;  // q|k|v, each [64][QKV_ROW]
    float* wsb  = sm + WSU_OFF;  // weight K-tile [16][WS_STRIDE]  /  S [64][S_STRIDE]
    float* rpbs = sm + RPB_OFF;  // rpb table [225][6]

    const int tid = threadIdx.x;
    const int win = blockIdx.x;
    const int b   = win >> 10;
    const int wy  = (win >> 5) & 31;
    const int wx  = win & 31;
    const long pix0 = ((long)b * H_ + (long)wy * WS_) * W_ + (long)wx * WS_;

    // ---------------- Phase 1: stage x window (transposed) + rpb table ----------------
    #pragma unroll 2
    for (int i = tid; i < T_ * 48; i += 256) {
        const int t  = i / 48;
        const int c4 = (i % 48) * 4;
        const int py = t >> 3, px = t & 7;
        const float4 v = *(const float4*)(x + (pix0 + (long)py * W_ + px) * C_ + c4);
        xs[(c4 + 0) * XS_STRIDE + t] = v.x;
        xs[(c4 + 1) * XS_STRIDE + t] = v.y;
        xs[(c4 + 2) * XS_STRIDE + t] = v.z;
        xs[(c4 + 3) * XS_STRIDE + t] = v.w;
    }
    for (int i = tid; i < 225 * NH_; i += 256) rpbs[i] = rpb[i];

    const int gtx  = tid % 24;       // 24 col-groups of 8 -> 192 cols
    const int gty  = tid / 24;       // 8 row-groups of 8  -> 64 rows (gty<8 active)
    const bool gact = (gty < 8);

    // ---------------- Phase 2: QKV = x @ qkv_w^T  (3 passes of 64x192, K=192) ----------------
    for (int s = 0; s < 3; ++s) {
        float acc[8][8];
        #pragma unroll
        for (int i = 0; i < 8; ++i)
            #pragma unroll
            for (int j = 0; j < 8; ++j) acc[i][j] = 0.f;

        const float* wptr = qkv_w + (size_t)s * 192 * 192;
        for (int kc = 0; kc < 192; kc += 16) {
            __syncthreads();
            // stage weight K-tile: wsb[kk][c] = wptr[c*192 + kc + kk]
            #pragma unroll 3
            for (int i = tid; i < 768; i += 256) {
                const int c  = i >> 2;
                const int k4 = (i & 3) * 4;
                const float4 v = *(const float4*)(wptr + c * 192 + kc + k4);
                wsb[(k4 + 0) * WS_STRIDE + c] = v.x;
                wsb[(k4 + 1) * WS_STRIDE + c] = v.y;
                wsb[(k4 + 2) * WS_STRIDE + c] = v.z;
                wsb[(k4 + 3) * WS_STRIDE + c] = v.w;
            }
            __syncthreads();
            if (gact) {
                const float* xcol = xs + kc * XS_STRIDE + gty * 8;
                const float* wrow = wsb + gtx * 8;
                #pragma unroll
                for (int kk = 0; kk < 16; ++kk) {
                    const float4 a0 = *(const float4*)(xcol + kk * XS_STRIDE);
                    const float4 a1 = *(const float4*)(xcol + kk * XS_STRIDE + 4);
                    const float4 b0 = *(const float4*)(wrow + kk * WS_STRIDE);
                    const float4 b1 = *(const float4*)(wrow + kk * WS_STRIDE + 4);
                    const float a[8]  = {a0.x, a0.y, a0.z, a0.w, a1.x, a1.y, a1.z, a1.w};
                    const float bb[8] = {b0.x, b0.y, b0.z, b0.w, b1.x, b1.y, b1.z, b1.w};
                    #pragma unroll
                    for (int i = 0; i < 8; ++i)
                        #pragma unroll
                        for (int j = 0; j < 8; ++j)
                            acc[i][j] = fmaf(a[i], bb[j], acc[i][j]);
                }
            }
        }
        if (gact) {
            const float mul = (s == 0) ? 0.17677669529663687f : 1.0f;  // q pre-scaled by 1/sqrt(hd)
            float* dst = qkvs + (size_t)s * T_ * QKV_ROW;
            #pragma unroll
            for (int i = 0; i < 8; ++i)
                #pragma unroll
                for (int j = 0; j < 8; ++j)
                    dst[(gty * 8 + i) * QKV_ROW + gtx * 8 + j] = acc[i][j] * mul;
        }
    }
    __syncthreads();

    // ---------------- Phase 3: per-head attention ----------------
    const float* q_s = qkvs;
    const float* k_s = qkvs + T_ * QKV_ROW;
    const float* v_s = qkvs + 2 * T_ * QKV_ROW;
    float* S  = wsb;   // [64][S_STRIDE]
    float* ao = xs;    // attn output transposed [c][t], reuse xs region

    const int si = (tid >> 4) * 4;    // 4 rows per thread
    const int sj = (tid & 15) * 4;    // 4 cols per thread (S phase)
    const int ci = (tid & 15) * 2;    // 2 cols per thread (PV phase)

    for (int h = 0; h < NH_; ++h) {
        const int hc = h * HD_;
        // ---- S = q @ k^T + bias ----
        {
            float acc[4][4];
            #pragma unroll
            for (int i = 0; i < 4; ++i)
                #pragma unroll
                for (int j = 0; j < 4; ++j) acc[i][j] = 0.f;
            #pragma unroll 8
            for (int d = 0; d < HD_; ++d) {
                float a[4], bb[4];
                #pragma unroll
                for (int i = 0; i < 4; ++i) a[i]  = q_s[(si + i) * QKV_ROW + hc + d];
                #pragma unroll
                for (int j = 0; j < 4; ++j) bb[j] = k_s[(sj + j) * QKV_ROW + hc + d];
                #pragma unroll
                for (int i = 0; i < 4; ++i)
                    #pragma unroll
                    for (int j = 0; j < 4; ++j)
                        acc[i][j] = fmaf(a[i], bb[j], acc[i][j]);
            }
            #pragma unroll
            for (int i = 0; i < 4; ++i) {
                const int p = si + i;
                #pragma unroll
                for (int j = 0; j < 4; ++j) {
                    const int qq  = sj + j;
                    const int dy  = (p >> 3) - (qq >> 3);
                    const int dx  = (p & 7)  - (qq & 7);
                    const int idx = (dy + 7) * 15 + (dx + 7);
                    S[p * S_STRIDE + qq] = acc[i][j] + rpbs[idx * NH_ + h];
                }
            }
        }
        __syncthreads();
        // ---- row softmax (stable) ----
        if (tid < 64) {
            float* row = S + tid * S_STRIDE;
            float m = -1e30f;
            #pragma unroll 8
            for (int j = 0; j < 64; ++j) m = fmaxf(m, row[j]);
            float sum = 0.f;
            #pragma unroll 8
            for (int j = 0; j < 64; ++j) { const float e = __expf(row[j] - m); row[j] = e; sum += e; }
            const float inv = 1.f / sum;
            #pragma unroll 8
            for (int j = 0; j < 64; ++j) row[j] *= inv;
        }
        __syncthreads();
        // ---- O = P @ v, store transposed into ao ----
        {
            float o0[4], o1[4];
            #pragma unroll
            for (int i = 0; i < 4; ++i) { o0[i] = 0.f; o1[i] = 0.f; }
            #pragma unroll 4
            for (int j = 0; j < 64; ++j) {
                const float v0 = v_s[j * QKV_ROW + hc + ci];
                const float v1 = v_s[j * QKV_ROW + hc + ci + 1];
                #pragma unroll
                for (int i = 0; i < 4; ++i) {
                    const float p = S[(si + i) * S_STRIDE + j];
                    o0[i] = fmaf(p, v0, o0[i]);
                    o1[i] = fmaf(p, v1, o1[i]);
                }
            }
            #pragma unroll
            for (int i = 0; i < 4; ++i) {
                ao[(hc + ci + 0) * XS_STRIDE + si + i] = o0[i];
                ao[(hc + ci + 1) * XS_STRIDE + si + i] = o1[i];
            }
        }
        __syncthreads();
    }

    // ---------------- Phase 4: proj = attn_out @ proj_w^T + b, scatter to output ----------------
    {
        float acc[8][8];
        #pragma unroll
        for (int i = 0; i < 8; ++i)
            #pragma unroll
            for (int j = 0; j < 8; ++j) acc[i][j] = 0.f;

        for (int kc = 0; kc < 192; kc += 16) {
            __syncthreads();
            #pragma unroll 3
            for (int i = tid; i < 768; i += 256) {
                const int c  = i >> 2;
                const int k4 = (i & 3) * 4;
                const float4 v = *(const float4*)(proj_w + c * 192 + kc + k4);
                wsb[(k4 + 0) * WS_STRIDE + c] = v.x;
                wsb[(k4 + 1) * WS_STRIDE + c] = v.y;
                wsb[(k4 + 2) * WS_STRIDE + c] = v.z;
                wsb[(k4 + 3) * WS_STRIDE + c] = v.w;
            }
            __syncthreads();
            if (gact) {
                const float* acol = ao + kc * XS_STRIDE + gty * 8;
                const float* wrow = wsb + gtx * 8;
                #pragma unroll
                for (int kk = 0; kk < 16; ++kk) {
                    const float4 a0 = *(const float4*)(acol + kk * XS_STRIDE);
                    const float4 a1 = *(const float4*)(acol + kk * XS_STRIDE + 4);
                    const float4 b0 = *(const float4*)(wrow + kk * WS_STRIDE);
                    const float4 b1 = *(const float4*)(wrow + kk * WS_STRIDE + 4);
                    const float a[8]  = {a0.x, a0.y, a0.z, a0.w, a1.x, a1.y, a1.z, a1.w};
                    const float bb[8] = {b0.x, b0.y, b0.z, b0.w, b1.x, b1.y, b1.z, b1.w};
                    #pragma unroll
                    for (int i = 0; i < 8; ++i)
                        #pragma unroll
                        for (int j = 0; j < 8; ++j)
                            acc[i][j] = fmaf(a[i], bb[j], acc[i][j]);
                }
            }
        }
        if (gact) {
            float pb[8];
            #pragma unroll
            for (int j = 0; j < 8; ++j) pb[j] = proj_b[gtx * 8 + j];
            #pragma unroll
            for (int i = 0; i < 8; ++i) {
                const int t  = gty * 8 + i;
                const int py = t >> 3, px = t & 7;
                float* dst = outp + (pix0 + (long)py * W_ + px) * C_ + gtx * 8;
                float4 r0, r1;
                r0.x = acc[i][0] + pb[0]; r0.y = acc[i][1] + pb[1];
                r0.z = acc[i][2] + pb[2]; r0.w = acc[i][3] + pb[3];
                r1.x = acc[i][4] + pb[4]; r1.y = acc[i][5] + pb[5];
                r1.z = acc[i][6] + pb[6]; r1.w = acc[i][7] + pb[7];
                *(float4*)(dst)     = r0;
                *(float4*)(dst + 4) = r1;
            }
        }
    }
}

extern "C" void kernel_launch(void* const* d_in, const int* in_sizes, int n_in,
                              void* d_out, int out_size)
{
    const float* x      = (const float*)d_in[0];
    const float* qkv_w  = (const float*)d_in[1];
    const float* proj_w = (const float*)d_in[2];
    const float* proj_b = (const float*)d_in[3];
    const float* rpb    = (const float*)d_in[4];
    // d_in[5], d_in[6] are H, W scalars (fixed 256x256 for this problem)

    cudaFuncSetAttribute(swin_win_attn_kernel,
                         cudaFuncAttributeMaxDynamicSharedMemorySize, SMEM_BYTES);

    const int n_windows = B_ * (H_ / WS_) * (W_ / WS_);  // 4096
    swin_win_attn_kernel<<<n_windows, 256, SMEM_BYTES>>>(
        x, qkv_w, proj_w, proj_b, rpb, (float*)d_out);
}